// round 1
// baseline (speedup 1.0000x reference)
#include <cuda_runtime.h>
#include <cuda_bf16.h>
#include <math.h>

// Problem constants (fixed shapes)
#define NTOK 4096      // B*T
#define CDIM 1024      // C
#define NEXP 64        // E
#define TOPK 8
#define CAP  1024      // 2*N*K/E
#define HS   1024      // shared hidden
#define HE   512       // expert hidden

// ---------------- scratch (device globals; no allocation) ----------------
__device__ float g_xbuf[(size_t)NEXP * CAP * CDIM];       // 256 MB: permuted tokens
__device__ float g_eup [(size_t)NEXP * CAP * (2*HE)];     // 256 MB: expert up output
__device__ float g_eh  [(size_t)NEXP * CAP * HE];         // 128 MB: expert swiglu
__device__ float g_eoe [(size_t)NEXP * CAP * CDIM];       // 256 MB: expert down output
__device__ float g_sup [(size_t)NTOK * (2*HS)];           // 32 MB : shared up output
__device__ float g_sh  [(size_t)NTOK * HS];               // 16 MB : shared swiglu
__device__ int   g_counts[NEXP];
__device__ int   g_slots[NTOK * TOPK];
__device__ float g_wts  [NTOK * TOPK];

// ---------------- zero counts ----------------
__global__ void zero_counts_kernel(int* counts) {
    if (threadIdx.x < NEXP) counts[threadIdx.x] = 0;
}

// ---------------- router: logits -> sigmoid -> top8 -> slot assign -> scatter ----------------
__global__ __launch_bounds__(256) void router_kernel(
    const float* __restrict__ x, const float* __restrict__ rw,
    const float* __restrict__ bias,
    int* __restrict__ counts, int* __restrict__ slots,
    float* __restrict__ wts, float* __restrict__ xbuf)
{
    int t = blockIdx.x;
    int tid = threadIdx.x;
    __shared__ float xs[CDIM];
    __shared__ float partial[256];
    __shared__ float sc[NEXP];      // sigmoid scores
    __shared__ float sb[NEXP];      // biased scores, destructible
    __shared__ int   tslot[TOPK];

    for (int i = tid; i < CDIM; i += 256) xs[i] = x[(size_t)t * CDIM + i];
    __syncthreads();

    // 4 partial dots per expert (tid = part*64 + e)
    int e = tid & 63, part = tid >> 6;
    float acc = 0.f;
    const float* rwp = rw + (size_t)(part * 256) * NEXP + e;
    #pragma unroll 8
    for (int c = 0; c < 256; c++) acc += xs[part * 256 + c] * rwp[(size_t)c * NEXP];
    partial[tid] = acc;
    __syncthreads();
    if (tid < NEXP) {
        float v = partial[tid] + partial[tid + 64] + partial[tid + 128] + partial[tid + 192];
        float s = 1.f / (1.f + __expf(-v));
        sc[tid] = s;
        sb[tid] = s + bias[tid];
    }
    __syncthreads();

    if (tid == 0) {
        float wsum = 0.f;
        int   eid[TOPK]; float ww[TOPK];
        #pragma unroll
        for (int k = 0; k < TOPK; k++) {
            int best = 0; float bv = sb[0];
            for (int i = 1; i < NEXP; i++) { float v = sb[i]; if (v > bv) { bv = v; best = i; } }
            sb[best] = -1e30f;
            eid[k] = best; ww[k] = sc[best]; wsum += sc[best];
        }
        float inv = 1.f / wsum;
        #pragma unroll
        for (int k = 0; k < TOPK; k++) {
            int pos  = atomicAdd(&counts[eid[k]], 1);
            int slot = eid[k] * CAP + pos;
            tslot[k] = slot;
            slots[t * TOPK + k] = slot;
            wts  [t * TOPK + k] = ww[k] * inv;
        }
    }
    __syncthreads();

    // scatter token row to its 8 expert slots
    #pragma unroll
    for (int k = 0; k < TOPK; k++) {
        float* dst = xbuf + (size_t)tslot[k] * CDIM;
        for (int i = tid; i < CDIM; i += 256) dst[i] = xs[i];
    }
}

// ---------------- generic tiled SGEMM (row-major A[MxK], B[KxN] -> C[MxN], ldc=N) ----------------
// Optional per-z strides (grouped) and per-z M from counts (tile skip).
#define BM 128
#define BN 128
#define BKK 16

__global__ __launch_bounds__(256) void sgemm_kernel(
    const float* __restrict__ A, const float* __restrict__ B, float* __restrict__ C,
    int M, int N, int K,
    long sAz, long sBz, long sCz, const int* __restrict__ counts)
{
    __shared__ float As[BKK][BM];
    __shared__ float Bs[BKK][BN];

    int z = blockIdx.z;
    if (counts) M = counts[z];
    int m0 = blockIdx.y * BM;
    if (m0 >= M) return;
    int n0 = blockIdx.x * BN;
    A += (long)z * sAz; B += (long)z * sBz; C += (long)z * sCz;

    int tid = threadIdx.x;
    int tx = tid & 15, ty = tid >> 4;

    float accum[8][8];
    #pragma unroll
    for (int i = 0; i < 8; i++)
        #pragma unroll
        for (int j = 0; j < 8; j++) accum[i][j] = 0.f;

    for (int k0 = 0; k0 < K; k0 += BKK) {
        // A tile 128x16 (512 float4)
        #pragma unroll
        for (int i = tid; i < (BM * BKK) / 4; i += 256) {
            int r  = i >> 2;
            int c4 = i & 3;
            float4 v = make_float4(0.f, 0.f, 0.f, 0.f);
            if (m0 + r < M)
                v = *(const float4*)(A + (long)(m0 + r) * K + k0 + c4 * 4);
            As[c4 * 4 + 0][r] = v.x;
            As[c4 * 4 + 1][r] = v.y;
            As[c4 * 4 + 2][r] = v.z;
            As[c4 * 4 + 3][r] = v.w;
        }
        // B tile 16x128 (512 float4)
        #pragma unroll
        for (int i = tid; i < (BKK * BN) / 4; i += 256) {
            int r  = i >> 5;
            int c4 = i & 31;
            float4 v = *(const float4*)(B + (long)(k0 + r) * N + n0 + c4 * 4);
            *(float4*)(&Bs[r][c4 * 4]) = v;
        }
        __syncthreads();

        #pragma unroll
        for (int kk = 0; kk < BKK; kk++) {
            float ar[8], br[8];
            #pragma unroll
            for (int i = 0; i < 8; i++) ar[i] = As[kk][ty * 8 + i];
            #pragma unroll
            for (int j = 0; j < 8; j++) br[j] = Bs[kk][tx * 8 + j];
            #pragma unroll
            for (int i = 0; i < 8; i++)
                #pragma unroll
                for (int j = 0; j < 8; j++)
                    accum[i][j] = fmaf(ar[i], br[j], accum[i][j]);
        }
        __syncthreads();
    }

    #pragma unroll
    for (int i = 0; i < 8; i++) {
        int r = m0 + ty * 8 + i;
        if (r < M) {
            float4 v0 = make_float4(accum[i][0], accum[i][1], accum[i][2], accum[i][3]);
            float4 v1 = make_float4(accum[i][4], accum[i][5], accum[i][6], accum[i][7]);
            *(float4*)(C + (long)r * N + n0 + tx * 8)     = v0;
            *(float4*)(C + (long)r * N + n0 + tx * 8 + 4) = v1;
        }
    }
}

// ---------------- SwiGLU: h[r][j] = silu(up[r][half+j]) * up[r][j] ----------------
__global__ void swiglu_kernel(const float* __restrict__ up, float* __restrict__ h,
                              long total, int half, int ldup)
{
    long idx = (long)blockIdx.x * blockDim.x + threadIdx.x;
    if (idx >= total) return;
    long r = idx / half;
    int  j = (int)(idx - r * half);
    float y = up[r * ldup + j];
    float g = up[r * ldup + half + j];
    float s = g / (1.f + __expf(-g));
    h[r * half + j] = s * y;
}

// ---------------- combine: out[t] = shared(out) + sum_k w * oe[slot_k] ----------------
__global__ __launch_bounds__(256) void combine_kernel(
    const float* __restrict__ oe, const int* __restrict__ slots,
    const float* __restrict__ wts, float* __restrict__ out)
{
    int t = blockIdx.x;
    int tid = threadIdx.x;
    int   sl[TOPK];
    float ww[TOPK];
    #pragma unroll
    for (int k = 0; k < TOPK; k++) { sl[k] = slots[t * TOPK + k]; ww[k] = wts[t * TOPK + k]; }
    for (int c = tid; c < CDIM; c += 256) {
        float acc = out[(size_t)t * CDIM + c];
        #pragma unroll
        for (int k = 0; k < TOPK; k++)
            acc += ww[k] * oe[(size_t)sl[k] * CDIM + c];
        out[(size_t)t * CDIM + c] = acc;
    }
}

// ---------------- launch ----------------
extern "C" void kernel_launch(void* const* d_in, const int* in_sizes, int n_in,
                              void* d_out, int out_size)
{
    const float* x       = (const float*)d_in[0];   // (2,2048,1024)
    const float* rw      = (const float*)d_in[1];   // (1024,64)
    const float* bias    = (const float*)d_in[2];   // (64,)
    const float* sup_w   = (const float*)d_in[3];   // (1024,2048)
    const float* sdown_w = (const float*)d_in[4];   // (1024,1024)
    const float* eup_w   = (const float*)d_in[5];   // (64,1024,1024)
    const float* edown_w = (const float*)d_in[6];   // (64,512,1024)
    float* out = (float*)d_out;
    (void)in_sizes; (void)n_in; (void)out_size;

    float *xbuf, *eup, *eh, *eoe, *sup, *sh, *wts;
    int *counts, *slots;
    cudaGetSymbolAddress((void**)&xbuf,   g_xbuf);
    cudaGetSymbolAddress((void**)&eup,    g_eup);
    cudaGetSymbolAddress((void**)&eh,     g_eh);
    cudaGetSymbolAddress((void**)&eoe,    g_eoe);
    cudaGetSymbolAddress((void**)&sup,    g_sup);
    cudaGetSymbolAddress((void**)&sh,     g_sh);
    cudaGetSymbolAddress((void**)&counts, g_counts);
    cudaGetSymbolAddress((void**)&slots,  g_slots);
    cudaGetSymbolAddress((void**)&wts,    g_wts);

    // 1. routing
    zero_counts_kernel<<<1, 64>>>(counts);
    router_kernel<<<NTOK, 256>>>(x, rw, bias, counts, slots, wts, xbuf);

    // 2. shared expert: up GEMM -> swiglu -> down GEMM (writes d_out)
    sgemm_kernel<<<dim3(2 * HS / BN, NTOK / BM, 1), 256>>>(
        x, sup_w, sup, NTOK, 2 * HS, CDIM, 0, 0, 0, nullptr);
    {
        long total = (long)NTOK * HS;
        swiglu_kernel<<<(unsigned)((total + 255) / 256), 256>>>(sup, sh, total, HS, 2 * HS);
    }
    sgemm_kernel<<<dim3(CDIM / BN, NTOK / BM, 1), 256>>>(
        sh, sdown_w, out, NTOK, CDIM, HS, 0, 0, 0, nullptr);

    // 3. grouped expert GEMMs (count-aware tile skipping)
    sgemm_kernel<<<dim3(2 * HE / BN, CAP / BM, NEXP), 256>>>(
        xbuf, eup_w, eup, CAP, 2 * HE, CDIM,
        (long)CAP * CDIM, (long)CDIM * (2 * HE), (long)CAP * (2 * HE), counts);
    {
        long total = (long)NEXP * CAP * HE;
        swiglu_kernel<<<(unsigned)((total + 255) / 256), 256>>>(eup, eh, total, HE, 2 * HE);
    }
    sgemm_kernel<<<dim3(CDIM / BN, CAP / BM, NEXP), 256>>>(
        eh, edown_w, eoe, CAP, CDIM, HE,
        (long)CAP * HE, (long)HE * CDIM, (long)CAP * CDIM, counts);

    // 4. weighted combine into shared-expert output
    combine_kernel<<<NTOK, 256>>>(eoe, slots, wts, out);
}

// round 3
// speedup vs baseline: 2.1894x; 2.1894x over previous
#include <cuda_runtime.h>
#include <cuda_bf16.h>
#include <cstdint>

// ---------------- shapes ----------------
#define NTOK 4096
#define CDIM 1024
#define NEXP 64
#define TOPK 8
#define CAP  1024
#define HS   1024
#define HE   512

// ---------------- helpers ----------------
__device__ __forceinline__ uint32_t smem_u32(const void* p) {
    uint32_t a;
    asm("{ .reg .u64 t; cvta.to.shared.u64 t, %1; cvt.u32.u64 %0, t; }" : "=r"(a) : "l"(p));
    return a;
}
#define CP_ASYNC16(dst, src) \
    asm volatile("cp.async.cg.shared.global [%0], [%1], 16;" :: "r"(dst), "l"(src))
#define CP_COMMIT() asm volatile("cp.async.commit_group;" ::: "memory")
#define CP_WAIT1()  asm volatile("cp.async.wait_group 1;" ::: "memory")

__device__ __forceinline__ void ldm_x4(uint32_t* r, uint32_t addr) {
    asm volatile("ldmatrix.sync.aligned.m8n8.x4.shared.b16 {%0,%1,%2,%3}, [%4];"
        : "=r"(r[0]), "=r"(r[1]), "=r"(r[2]), "=r"(r[3]) : "r"(addr));
}
__device__ __forceinline__ void mma_bf16(float* d, const uint32_t* a, const uint32_t* b) {
    asm volatile(
        "mma.sync.aligned.m16n8k16.row.col.f32.bf16.bf16.f32 "
        "{%0,%1,%2,%3}, {%4,%5,%6,%7}, {%8,%9}, {%0,%1,%2,%3};"
        : "+f"(d[0]), "+f"(d[1]), "+f"(d[2]), "+f"(d[3])
        : "r"(a[0]), "r"(a[1]), "r"(a[2]), "r"(a[3]), "r"(b[0]), "r"(b[1]));
}
__device__ __forceinline__ void split_f32(float v, __nv_bfloat16& h, __nv_bfloat16& l) {
    h = __float2bfloat16(v);
    l = __float2bfloat16(v - __bfloat162float(h));
}

// ---------------- scratch (device globals) ----------------
__device__ __nv_bfloat16 g_xh  [(size_t)NTOK * CDIM];
__device__ __nv_bfloat16 g_xl  [(size_t)NTOK * CDIM];
__device__ __nv_bfloat16 g_xbh [(size_t)NEXP * CAP * CDIM];
__device__ __nv_bfloat16 g_xbl [(size_t)NEXP * CAP * CDIM];
__device__ float         g_sup [(size_t)NTOK * 2 * HS];
__device__ __nv_bfloat16 g_shh [(size_t)NTOK * HS];
__device__ __nv_bfloat16 g_shl [(size_t)NTOK * HS];
__device__ float         g_eup [(size_t)NEXP * CAP * 2 * HE];
__device__ __nv_bfloat16 g_ehh [(size_t)NEXP * CAP * HE];
__device__ __nv_bfloat16 g_ehl [(size_t)NEXP * CAP * HE];
__device__ float         g_eoe [(size_t)NEXP * CAP * CDIM];
__device__ __nv_bfloat16 g_supt_h [(size_t)(2 * HS) * CDIM];
__device__ __nv_bfloat16 g_supt_l [(size_t)(2 * HS) * CDIM];
__device__ __nv_bfloat16 g_sdnt_h [(size_t)CDIM * HS];
__device__ __nv_bfloat16 g_sdnt_l [(size_t)CDIM * HS];
__device__ __nv_bfloat16 g_eupt_h [(size_t)NEXP * (2 * HE) * CDIM];
__device__ __nv_bfloat16 g_eupt_l [(size_t)NEXP * (2 * HE) * CDIM];
__device__ __nv_bfloat16 g_ednt_h [(size_t)NEXP * CDIM * HE];
__device__ __nv_bfloat16 g_ednt_l [(size_t)NEXP * CDIM * HE];
__device__ int   g_counts[NEXP];
__device__ int   g_slots[NTOK * TOPK];
__device__ float g_wts [NTOK * TOPK];

// ---------------- small kernels ----------------
__global__ void zero_counts_kernel(int* counts) {
    if (threadIdx.x < NEXP) counts[threadIdx.x] = 0;
}

__global__ void split_x_kernel(const float* __restrict__ x,
                               __nv_bfloat16* __restrict__ xh, __nv_bfloat16* __restrict__ xl) {
    size_t i4 = (size_t)blockIdx.x * blockDim.x + threadIdx.x;
    if (i4 >= (size_t)NTOK * CDIM / 4) return;
    float4 v = *(const float4*)(x + i4 * 4);
    __nv_bfloat16 h[4], l[4];
    split_f32(v.x, h[0], l[0]); split_f32(v.y, h[1], l[1]);
    split_f32(v.z, h[2], l[2]); split_f32(v.w, h[3], l[3]);
    *(uint2*)(xh + i4 * 4) = *(uint2*)h;
    *(uint2*)(xl + i4 * 4) = *(uint2*)l;
}

// transpose + split: in [K][N] fp32 -> oh/ol [N][K] bf16
__global__ void transpose_split_kernel(const float* __restrict__ in,
                                       __nv_bfloat16* __restrict__ oh, __nv_bfloat16* __restrict__ ol,
                                       int K, int N, long inz, long outz) {
    __shared__ float tile[32][33];
    int z = blockIdx.z;
    in += (size_t)z * inz; oh += (size_t)z * outz; ol += (size_t)z * outz;
    int n0 = blockIdx.x * 32, k0 = blockIdx.y * 32;
    int tx = threadIdx.x, ty = threadIdx.y;
    #pragma unroll
    for (int i = 0; i < 32; i += 8)
        tile[ty + i][tx] = in[(size_t)(k0 + ty + i) * N + n0 + tx];
    __syncthreads();
    #pragma unroll
    for (int i = 0; i < 32; i += 8) {
        float v = tile[tx][ty + i];
        size_t o = (size_t)(n0 + ty + i) * K + k0 + tx;
        __nv_bfloat16 h, l; split_f32(v, h, l);
        oh[o] = h; ol[o] = l;
    }
}

// ---------------- router ----------------
__global__ __launch_bounds__(256) void router_kernel(
    const float* __restrict__ x, const float* __restrict__ rw, const float* __restrict__ bias,
    int* __restrict__ counts, int* __restrict__ slots, float* __restrict__ wts,
    __nv_bfloat16* __restrict__ xbh, __nv_bfloat16* __restrict__ xbl) {
    int t = blockIdx.x;
    int tid = threadIdx.x;
    __shared__ float xs[CDIM];
    __shared__ float partial[256];
    __shared__ float sc[NEXP];
    __shared__ float sb[NEXP];
    __shared__ int   tslot[TOPK];

    for (int i = tid; i < CDIM; i += 256) xs[i] = x[(size_t)t * CDIM + i];
    __syncthreads();

    int e = tid & 63, part = tid >> 6;
    float acc = 0.f;
    const float* rwp = rw + (size_t)(part * 256) * NEXP + e;
    #pragma unroll 8
    for (int c = 0; c < 256; c++) acc += xs[part * 256 + c] * rwp[(size_t)c * NEXP];
    partial[tid] = acc;
    __syncthreads();
    if (tid < NEXP) {
        float v = partial[tid] + partial[tid + 64] + partial[tid + 128] + partial[tid + 192];
        float s = 1.f / (1.f + __expf(-v));
        sc[tid] = s;
        sb[tid] = s + bias[tid];
    }
    __syncthreads();

    if (tid == 0) {
        float wsum = 0.f;
        int eid[TOPK]; float ww[TOPK];
        #pragma unroll
        for (int k = 0; k < TOPK; k++) {
            int best = 0; float bv = sb[0];
            for (int i = 1; i < NEXP; i++) { float v = sb[i]; if (v > bv) { bv = v; best = i; } }
            sb[best] = -1e30f;
            eid[k] = best; ww[k] = sc[best]; wsum += sc[best];
        }
        float inv = 1.f / wsum;
        #pragma unroll
        for (int k = 0; k < TOPK; k++) {
            int pos  = atomicAdd(&counts[eid[k]], 1);
            int slot = eid[k] * CAP + pos;
            tslot[k] = slot;
            slots[t * TOPK + k] = slot;
            wts  [t * TOPK + k] = ww[k] * inv;
        }
    }
    __syncthreads();

    #pragma unroll
    for (int k = 0; k < TOPK; k++) {
        __nv_bfloat16* dh = xbh + (size_t)tslot[k] * CDIM;
        __nv_bfloat16* dl = xbl + (size_t)tslot[k] * CDIM;
        for (int i = tid; i < CDIM; i += 256) {
            __nv_bfloat16 h, l; split_f32(xs[i], h, l);
            dh[i] = h; dl[i] = l;
        }
    }
}

// ---------------- mma.sync GEMM: D[M,N] = A[M,K] @ Bt[N,K]^T (hi/lo split, fp32 accum) ----------------
// CTA tile 128x128, Kc=32, 2-stage cp.async pipeline.
// Smem per tensor tile: 128 rows x (32+8) bf16 = 10240 B; stage = 40960 B; 2 stages = 81920 B.
#define LDSH 40
#define TEN_BYTES 10240
#define STG_BYTES 40960

__device__ __forceinline__ void issue_stage(
    uint32_t sdst, const __nv_bfloat16* pAh, const __nv_bfloat16* pAl,
    const __nv_bfloat16* pBh, const __nv_bfloat16* pBl,
    int K, int kc, int tid)
{
    int kcol = kc * 32;
    #pragma unroll
    for (int c2 = 0; c2 < 2; c2++) {
        int u = tid + c2 * 256;
        int row = u >> 2, c4 = u & 3;
        uint32_t so = (uint32_t)(row * LDSH + c4 * 8) * 2;
        size_t go = (size_t)row * K + kcol + c4 * 8;
        CP_ASYNC16(sdst + 0 * TEN_BYTES + so, pAh + go);
        CP_ASYNC16(sdst + 1 * TEN_BYTES + so, pAl + go);
        CP_ASYNC16(sdst + 2 * TEN_BYTES + so, pBh + go);
        CP_ASYNC16(sdst + 3 * TEN_BYTES + so, pBl + go);
    }
}

__global__ __launch_bounds__(256, 1) void gemm_kernel(
    const __nv_bfloat16* __restrict__ Ah, const __nv_bfloat16* __restrict__ Al,
    const __nv_bfloat16* __restrict__ Bh, const __nv_bfloat16* __restrict__ Bl,
    float* __restrict__ D, int M, int N, int K,
    long sAz, long sBz, long sDz, const int* __restrict__ counts)
{
    extern __shared__ __align__(128) char smem[];
    int z = blockIdx.z;
    if (counts) M = counts[z];
    int m0 = blockIdx.y * 128;
    if (m0 >= M) return;
    int n0 = blockIdx.x * 128;
    Ah += (size_t)z * sAz; Al += (size_t)z * sAz;
    Bh += (size_t)z * sBz; Bl += (size_t)z * sBz;
    D  += (size_t)z * sDz;

    int tid = threadIdx.x, wid = tid >> 5, lane = tid & 31;
    int wm = (wid & 1) * 64;        // warp M offset in tile
    int wn = (wid >> 1) * 32;       // warp N offset in tile
    uint32_t sbase = smem_u32(smem);

    const __nv_bfloat16* pAh = Ah + (size_t)m0 * K;
    const __nv_bfloat16* pAl = Al + (size_t)m0 * K;
    const __nv_bfloat16* pBh = Bh + (size_t)n0 * K;
    const __nv_bfloat16* pBl = Bl + (size_t)n0 * K;

    float acc[4][4][4];
    #pragma unroll
    for (int i = 0; i < 4; i++)
        #pragma unroll
        for (int j = 0; j < 4; j++)
            #pragma unroll
            for (int r = 0; r < 4; r++) acc[i][j][r] = 0.f;

    const int nk = K >> 5;
    issue_stage(sbase,             pAh, pAl, pBh, pBl, K, 0, tid); CP_COMMIT();
    issue_stage(sbase + STG_BYTES, pAh, pAl, pBh, pBl, K, 1, tid); CP_COMMIT();

    // per-lane ldmatrix address components
    int laneA_row = lane & 15;
    int laneA_k   = ((lane >> 4) & 1) * 8;
    int laneB_n   = ((lane >> 4) & 1) * 8 + (lane & 7);
    int laneB_k   = ((lane >> 3) & 1) * 8;

    for (int kc = 0; kc < nk; kc++) {
        CP_WAIT1();
        __syncthreads();
        uint32_t sA = sbase + (kc & 1) * STG_BYTES;
        uint32_t sAl_ = sA + TEN_BYTES, sBh_ = sA + 2 * TEN_BYTES, sBl_ = sA + 3 * TEN_BYTES;

        #pragma unroll
        for (int kk = 0; kk < 32; kk += 16) {
            uint32_t ah[4][4], al[4][4], bh[4][2], bl[4][2];
            #pragma unroll
            for (int mi = 0; mi < 4; mi++) {
                uint32_t off = (uint32_t)((wm + mi * 16 + laneA_row) * LDSH + kk + laneA_k) * 2;
                ldm_x4(ah[mi], sA + off);
                ldm_x4(al[mi], sAl_ + off);
            }
            #pragma unroll
            for (int j = 0; j < 2; j++) {
                uint32_t off = (uint32_t)((wn + j * 16 + laneB_n) * LDSH + kk + laneB_k) * 2;
                uint32_t rb[4];
                ldm_x4(rb, sBh_ + off);
                bh[2 * j][0] = rb[0]; bh[2 * j][1] = rb[1];
                bh[2 * j + 1][0] = rb[2]; bh[2 * j + 1][1] = rb[3];
                ldm_x4(rb, sBl_ + off);
                bl[2 * j][0] = rb[0]; bl[2 * j][1] = rb[1];
                bl[2 * j + 1][0] = rb[2]; bl[2 * j + 1][1] = rb[3];
            }
            #pragma unroll
            for (int mi = 0; mi < 4; mi++)
                #pragma unroll
                for (int ni = 0; ni < 4; ni++) {
                    mma_bf16(acc[mi][ni], ah[mi], bh[ni]);
                    mma_bf16(acc[mi][ni], ah[mi], bl[ni]);
                    mma_bf16(acc[mi][ni], al[mi], bh[ni]);
                }
        }
        __syncthreads();
        if (kc + 2 < nk)
            issue_stage(sbase + (kc & 1) * STG_BYTES, pAh, pAl, pBh, pBl, K, kc + 2, tid);
        CP_COMMIT();
    }

    // epilogue: write fp32 accumulators
    int r0 = lane >> 2, c0 = (lane & 3) * 2;
    #pragma unroll
    for (int mi = 0; mi < 4; mi++) {
        #pragma unroll
        for (int ni = 0; ni < 4; ni++) {
            int row = m0 + wm + mi * 16 + r0;
            int col = n0 + wn + ni * 8 + c0;
            *(float2*)(D + (size_t)row * N + col) = make_float2(acc[mi][ni][0], acc[mi][ni][1]);
            *(float2*)(D + (size_t)(row + 8) * N + col) = make_float2(acc[mi][ni][2], acc[mi][ni][3]);
        }
    }
}

// ---------------- swiglu -> hi/lo bf16 pairs (optionally count-limited) ----------------
__global__ void swiglu_pair_kernel(const float* __restrict__ up,
                                   __nv_bfloat16* __restrict__ hh, __nv_bfloat16* __restrict__ hl,
                                   long nrows, int half, const int* __restrict__ counts) {
    size_t i4 = (size_t)blockIdx.x * blockDim.x + threadIdx.x;
    size_t total = (size_t)nrows * (half / 4);
    if (i4 >= total) return;
    size_t r = i4 / (half / 4);
    int j = (int)(i4 - r * (half / 4)) * 4;
    if (counts) {
        int e = (int)(r / CAP), pos = (int)(r % CAP);
        if (pos >= counts[e]) return;
    }
    const float* row = up + r * (size_t)(2 * half);
    float4 y = *(const float4*)(row + j);
    float4 g = *(const float4*)(row + half + j);
    float hv[4];
    hv[0] = y.x * (g.x / (1.f + __expf(-g.x)));
    hv[1] = y.y * (g.y / (1.f + __expf(-g.y)));
    hv[2] = y.z * (g.z / (1.f + __expf(-g.z)));
    hv[3] = y.w * (g.w / (1.f + __expf(-g.w)));
    __nv_bfloat16 h[4], l[4];
    #pragma unroll
    for (int i = 0; i < 4; i++) split_f32(hv[i], h[i], l[i]);
    *(uint2*)(hh + r * half + j) = *(uint2*)h;
    *(uint2*)(hl + r * half + j) = *(uint2*)l;
}

// ---------------- combine ----------------
__global__ __launch_bounds__(256) void combine_kernel(
    const float* __restrict__ oe, const int* __restrict__ slots,
    const float* __restrict__ wts, float* __restrict__ out) {
    int t = blockIdx.x;
    int c = threadIdx.x * 4;
    int sl[TOPK]; float ww[TOPK];
    #pragma unroll
    for (int k = 0; k < TOPK; k++) { sl[k] = slots[t * TOPK + k]; ww[k] = wts[t * TOPK + k]; }
    float4 acc = *(float4*)(out + (size_t)t * CDIM + c);
    #pragma unroll
    for (int k = 0; k < TOPK; k++) {
        float4 v = *(const float4*)(oe + (size_t)sl[k] * CDIM + c);
        acc.x += ww[k] * v.x; acc.y += ww[k] * v.y;
        acc.z += ww[k] * v.z; acc.w += ww[k] * v.w;
    }
    *(float4*)(out + (size_t)t * CDIM + c) = acc;
}

// ---------------- launch ----------------
extern "C" void kernel_launch(void* const* d_in, const int* in_sizes, int n_in,
                              void* d_out, int out_size) {
    const float* x       = (const float*)d_in[0];
    const float* rw      = (const float*)d_in[1];
    const float* bias    = (const float*)d_in[2];
    const float* sup_w   = (const float*)d_in[3];
    const float* sdown_w = (const float*)d_in[4];
    const float* eup_w   = (const float*)d_in[5];
    const float* edown_w = (const float*)d_in[6];
    float* out = (float*)d_out;
    (void)in_sizes; (void)n_in; (void)out_size;

    __nv_bfloat16 *xh, *xl, *xbh, *xbl, *shh, *shl, *ehh, *ehl;
    __nv_bfloat16 *supt_h, *supt_l, *sdnt_h, *sdnt_l, *eupt_h, *eupt_l, *ednt_h, *ednt_l;
    float *sup, *eup, *eoe, *wts;
    int *counts, *slots;
    cudaGetSymbolAddress((void**)&xh, g_xh);       cudaGetSymbolAddress((void**)&xl, g_xl);
    cudaGetSymbolAddress((void**)&xbh, g_xbh);     cudaGetSymbolAddress((void**)&xbl, g_xbl);
    cudaGetSymbolAddress((void**)&sup, g_sup);
    cudaGetSymbolAddress((void**)&shh, g_shh);     cudaGetSymbolAddress((void**)&shl, g_shl);
    cudaGetSymbolAddress((void**)&eup, g_eup);
    cudaGetSymbolAddress((void**)&ehh, g_ehh);     cudaGetSymbolAddress((void**)&ehl, g_ehl);
    cudaGetSymbolAddress((void**)&eoe, g_eoe);
    cudaGetSymbolAddress((void**)&supt_h, g_supt_h); cudaGetSymbolAddress((void**)&supt_l, g_supt_l);
    cudaGetSymbolAddress((void**)&sdnt_h, g_sdnt_h); cudaGetSymbolAddress((void**)&sdnt_l, g_sdnt_l);
    cudaGetSymbolAddress((void**)&eupt_h, g_eupt_h); cudaGetSymbolAddress((void**)&eupt_l, g_eupt_l);
    cudaGetSymbolAddress((void**)&ednt_h, g_ednt_h); cudaGetSymbolAddress((void**)&ednt_l, g_ednt_l);
    cudaGetSymbolAddress((void**)&counts, g_counts);
    cudaGetSymbolAddress((void**)&slots, g_slots);
    cudaGetSymbolAddress((void**)&wts, g_wts);

    cudaFuncSetAttribute(gemm_kernel, cudaFuncAttributeMaxDynamicSharedMemorySize, 2 * STG_BYTES);
    const int gsmem = 2 * STG_BYTES;

    // 1. routing + input splits
    zero_counts_kernel<<<1, 64>>>(counts);
    split_x_kernel<<<(NTOK * CDIM / 4 + 255) / 256, 256>>>(x, xh, xl);
    router_kernel<<<NTOK, 256>>>(x, rw, bias, counts, slots, wts, xbh, xbl);

    // 2. weight prep (transpose + hi/lo split)
    transpose_split_kernel<<<dim3(2 * HS / 32, CDIM / 32, 1), dim3(32, 8)>>>(
        sup_w, supt_h, supt_l, CDIM, 2 * HS, 0, 0);
    transpose_split_kernel<<<dim3(CDIM / 32, HS / 32, 1), dim3(32, 8)>>>(
        sdown_w, sdnt_h, sdnt_l, HS, CDIM, 0, 0);
    transpose_split_kernel<<<dim3(2 * HE / 32, CDIM / 32, NEXP), dim3(32, 8)>>>(
        eup_w, eupt_h, eupt_l, CDIM, 2 * HE, (long)CDIM * 2 * HE, (long)2 * HE * CDIM);
    transpose_split_kernel<<<dim3(CDIM / 32, HE / 32, NEXP), dim3(32, 8)>>>(
        edown_w, ednt_h, ednt_l, HE, CDIM, (long)HE * CDIM, (long)CDIM * HE);

    // 3. shared expert
    gemm_kernel<<<dim3(2 * HS / 128, NTOK / 128, 1), 256, gsmem>>>(
        xh, xl, supt_h, supt_l, sup, NTOK, 2 * HS, CDIM, 0, 0, 0, nullptr);
    swiglu_pair_kernel<<<(unsigned)(((size_t)NTOK * HS / 4 + 255) / 256), 256>>>(
        sup, shh, shl, NTOK, HS, nullptr);
    gemm_kernel<<<dim3(CDIM / 128, NTOK / 128, 1), 256, gsmem>>>(
        shh, shl, sdnt_h, sdnt_l, out, NTOK, CDIM, HS, 0, 0, 0, nullptr);

    // 4. expert grouped GEMMs
    gemm_kernel<<<dim3(2 * HE / 128, CAP / 128, NEXP), 256, gsmem>>>(
        xbh, xbl, eupt_h, eupt_l, eup, CAP, 2 * HE, CDIM,
        (long)CAP * CDIM, (long)(2 * HE) * CDIM, (long)CAP * 2 * HE, counts);
    swiglu_pair_kernel<<<(unsigned)(((size_t)NEXP * CAP * HE / 4 + 255) / 256), 256>>>(
        eup, ehh, ehl, (long)NEXP * CAP, HE, counts);
    gemm_kernel<<<dim3(CDIM / 128, CAP / 128, NEXP), 256, gsmem>>>(
        ehh, ehl, ednt_h, ednt_l, eoe, CAP, CDIM, HE,
        (long)CAP * HE, (long)CDIM * HE, (long)CAP * CDIM, counts);

    // 5. combine
    combine_kernel<<<NTOK, 256>>>(eoe, slots, wts, out);
}

// round 4
// speedup vs baseline: 2.2032x; 1.0063x over previous
#include <cuda_runtime.h>
#include <cuda_bf16.h>
#include <cstdint>

// ---------------- shapes ----------------
#define NTOK 4096
#define CDIM 1024
#define NEXP 64
#define TOPK 8
#define CAP  1024
#define HS   1024
#define HE   512

// ---------------- helpers ----------------
__device__ __forceinline__ uint32_t smem_u32(const void* p) {
    uint32_t a;
    asm("{ .reg .u64 t; cvta.to.shared.u64 t, %1; cvt.u32.u64 %0, t; }" : "=r"(a) : "l"(p));
    return a;
}
#define CP_ASYNC16(dst, src) \
    asm volatile("cp.async.cg.shared.global [%0], [%1], 16;" :: "r"(dst), "l"(src))
#define CP_COMMIT() asm volatile("cp.async.commit_group;" ::: "memory")
#define CP_WAIT2()  asm volatile("cp.async.wait_group 2;" ::: "memory")

__device__ __forceinline__ void ldm_x4(uint32_t* r, uint32_t addr) {
    asm volatile("ldmatrix.sync.aligned.m8n8.x4.shared.b16 {%0,%1,%2,%3}, [%4];"
        : "=r"(r[0]), "=r"(r[1]), "=r"(r[2]), "=r"(r[3]) : "r"(addr));
}
__device__ __forceinline__ void mma_bf16(float* d, const uint32_t* a, const uint32_t* b) {
    asm volatile(
        "mma.sync.aligned.m16n8k16.row.col.f32.bf16.bf16.f32 "
        "{%0,%1,%2,%3}, {%4,%5,%6,%7}, {%8,%9}, {%0,%1,%2,%3};"
        : "+f"(d[0]), "+f"(d[1]), "+f"(d[2]), "+f"(d[3])
        : "r"(a[0]), "r"(a[1]), "r"(a[2]), "r"(a[3]), "r"(b[0]), "r"(b[1]));
}
__device__ __forceinline__ void split_f32(float v, __nv_bfloat16& h, __nv_bfloat16& l) {
    h = __float2bfloat16(v);
    l = __float2bfloat16(v - __bfloat162float(h));
}

// ---------------- scratch (device globals) ----------------
__device__ __nv_bfloat16 g_xh  [(size_t)NTOK * CDIM];
__device__ __nv_bfloat16 g_xl  [(size_t)NTOK * CDIM];
__device__ __nv_bfloat16 g_shh [(size_t)NTOK * HS];
__device__ __nv_bfloat16 g_shl [(size_t)NTOK * HS];
__device__ __nv_bfloat16 g_ehh [(size_t)NEXP * CAP * HE];
__device__ __nv_bfloat16 g_ehl [(size_t)NEXP * CAP * HE];
__device__ float         g_eoe [(size_t)NEXP * CAP * CDIM];
__device__ __nv_bfloat16 g_supt_h [(size_t)(2 * HS) * CDIM];
__device__ __nv_bfloat16 g_supt_l [(size_t)(2 * HS) * CDIM];
__device__ __nv_bfloat16 g_sdnt_h [(size_t)CDIM * HS];
__device__ __nv_bfloat16 g_sdnt_l [(size_t)CDIM * HS];
__device__ __nv_bfloat16 g_eupt_h [(size_t)NEXP * (2 * HE) * CDIM];
__device__ __nv_bfloat16 g_eupt_l [(size_t)NEXP * (2 * HE) * CDIM];
__device__ __nv_bfloat16 g_ednt_h [(size_t)NEXP * CDIM * HE];
__device__ __nv_bfloat16 g_ednt_l [(size_t)NEXP * CDIM * HE];
__device__ int   g_counts[NEXP];
__device__ int   g_rowidx[NEXP * CAP];
__device__ int   g_slots[NTOK * TOPK];
__device__ float g_wts [NTOK * TOPK];

// ---------------- small kernels ----------------
__global__ void zero_counts_kernel(int* counts) {
    if (threadIdx.x < NEXP) counts[threadIdx.x] = 0;
}

// transpose + split: in [K][N] fp32 -> oh/ol [N][K] bf16.
// If half>0, output rows are (y,g)-interleaved: n<half -> 2n ; n>=half -> 2(n-half)+1.
__global__ void transpose_split_kernel(const float* __restrict__ in,
                                       __nv_bfloat16* __restrict__ oh, __nv_bfloat16* __restrict__ ol,
                                       int K, int N, long inz, long outz, int half) {
    __shared__ float tile[32][33];
    int z = blockIdx.z;
    in += (size_t)z * inz; oh += (size_t)z * outz; ol += (size_t)z * outz;
    int n0 = blockIdx.x * 32, k0 = blockIdx.y * 32;
    int tx = threadIdx.x, ty = threadIdx.y;
    #pragma unroll
    for (int i = 0; i < 32; i += 8)
        tile[ty + i][tx] = in[(size_t)(k0 + ty + i) * N + n0 + tx];
    __syncthreads();
    #pragma unroll
    for (int i = 0; i < 32; i += 8) {
        float v = tile[tx][ty + i];
        int n = n0 + ty + i;
        int nout = (half > 0) ? ((n < half) ? 2 * n : 2 * (n - half) + 1) : n;
        size_t o = (size_t)nout * K + k0 + tx;
        __nv_bfloat16 h, l; split_f32(v, h, l);
        oh[o] = h; ol[o] = l;
    }
}

// ---------------- router: scores, top-8, slot assign, write xh/xl + rowidx ----------------
__global__ __launch_bounds__(256) void router_kernel(
    const float* __restrict__ x, const float* __restrict__ rw, const float* __restrict__ bias,
    int* __restrict__ counts, int* __restrict__ rowidx,
    int* __restrict__ slots, float* __restrict__ wts,
    __nv_bfloat16* __restrict__ xh, __nv_bfloat16* __restrict__ xl) {
    int t = blockIdx.x;
    int tid = threadIdx.x;
    __shared__ float xs[CDIM];
    __shared__ float partial[256];
    __shared__ float sc[NEXP];
    __shared__ float sb[NEXP];

    for (int i = tid; i < CDIM; i += 256) xs[i] = x[(size_t)t * CDIM + i];
    __syncthreads();

    int e = tid & 63, part = tid >> 6;
    float acc = 0.f;
    const float* rwp = rw + (size_t)(part * 256) * NEXP + e;
    #pragma unroll 8
    for (int c = 0; c < 256; c++) acc += xs[part * 256 + c] * rwp[(size_t)c * NEXP];
    partial[tid] = acc;
    __syncthreads();
    if (tid < NEXP) {
        float v = partial[tid] + partial[tid + 64] + partial[tid + 128] + partial[tid + 192];
        float s = 1.f / (1.f + __expf(-v));
        sc[tid] = s;
        sb[tid] = s + bias[tid];
    }
    __syncthreads();

    if (tid == 0) {
        float wsum = 0.f;
        int eid[TOPK]; float ww[TOPK];
        #pragma unroll
        for (int k = 0; k < TOPK; k++) {
            int best = 0; float bv = sb[0];
            for (int i = 1; i < NEXP; i++) { float v = sb[i]; if (v > bv) { bv = v; best = i; } }
            sb[best] = -1e30f;
            eid[k] = best; ww[k] = sc[best]; wsum += sc[best];
        }
        float inv = 1.f / wsum;
        #pragma unroll
        for (int k = 0; k < TOPK; k++) {
            int pos  = atomicAdd(&counts[eid[k]], 1);
            int slot = eid[k] * CAP + pos;
            rowidx[slot] = t;
            slots[t * TOPK + k] = slot;
            wts  [t * TOPK + k] = ww[k] * inv;
        }
    }

    // write hi/lo split of this token row
    for (int i = tid; i < CDIM; i += 256) {
        __nv_bfloat16 h, l; split_f32(xs[i], h, l);
        xh[(size_t)t * CDIM + i] = h;
        xl[(size_t)t * CDIM + i] = l;
    }
}

// ---------------- mma.sync GEMM (hi/lo split, fp32 accum) ----------------
// CTA tile 128x128, Kc=32, 3-stage cp.async pipeline.
// Optional: row-gather for A (rowidx), fused SwiGLU epilogue (Hh/Hl bf16 pair out).
#define LDSH 40
#define TEN_BYTES 10240
#define STG_BYTES 40960

__device__ __forceinline__ void issue_stage(
    uint32_t sdst, const __nv_bfloat16* pAh, const __nv_bfloat16* pAl,
    const __nv_bfloat16* pBh, const __nv_bfloat16* pBl,
    int K, int kcol, int tid, int ar0, int ar1)
{
    {
        int u = tid;
        int row = u >> 2, c4 = u & 3;
        uint32_t so = (uint32_t)(row * LDSH + c4 * 8) * 2;
        size_t goA = (size_t)ar0 * K + kcol + c4 * 8;
        size_t goB = (size_t)row * K + kcol + c4 * 8;
        CP_ASYNC16(sdst + 0 * TEN_BYTES + so, pAh + goA);
        CP_ASYNC16(sdst + 1 * TEN_BYTES + so, pAl + goA);
        CP_ASYNC16(sdst + 2 * TEN_BYTES + so, pBh + goB);
        CP_ASYNC16(sdst + 3 * TEN_BYTES + so, pBl + goB);
    }
    {
        int u = tid + 256;
        int row = u >> 2, c4 = u & 3;
        uint32_t so = (uint32_t)(row * LDSH + c4 * 8) * 2;
        size_t goA = (size_t)ar1 * K + kcol + c4 * 8;
        size_t goB = (size_t)row * K + kcol + c4 * 8;
        CP_ASYNC16(sdst + 0 * TEN_BYTES + so, pAh + goA);
        CP_ASYNC16(sdst + 1 * TEN_BYTES + so, pAl + goA);
        CP_ASYNC16(sdst + 2 * TEN_BYTES + so, pBh + goB);
        CP_ASYNC16(sdst + 3 * TEN_BYTES + so, pBl + goB);
    }
}

__global__ __launch_bounds__(256, 1) void gemm_kernel(
    const __nv_bfloat16* __restrict__ Ah, const __nv_bfloat16* __restrict__ Al,
    const __nv_bfloat16* __restrict__ Bh, const __nv_bfloat16* __restrict__ Bl,
    float* __restrict__ D,
    __nv_bfloat16* __restrict__ Hh, __nv_bfloat16* __restrict__ Hl,
    int M, int N, int K,
    long sAz, long sBz, long sDz,
    const int* __restrict__ counts, const int* __restrict__ rowidx)
{
    extern __shared__ __align__(128) char smem[];
    int z = blockIdx.z;
    if (counts) M = counts[z];
    int m0 = blockIdx.y * 128;
    if (m0 >= M) return;
    int n0 = blockIdx.x * 128;
    Ah += (size_t)z * sAz; Al += (size_t)z * sAz;
    Bh += (size_t)z * sBz; Bl += (size_t)z * sBz;

    int tid = threadIdx.x, wid = tid >> 5, lane = tid & 31;
    int wm = (wid & 1) * 64;
    int wn = (wid >> 1) * 32;
    uint32_t sbase = smem_u32(smem);

    const __nv_bfloat16 *pAh, *pAl;
    int ar0, ar1;
    if (rowidx) {
        const int* ridx = rowidx + (size_t)z * CAP + m0;
        pAh = Ah; pAl = Al;
        ar0 = ridx[tid >> 2];
        ar1 = ridx[(tid + 256) >> 2];
    } else {
        pAh = Ah + (size_t)m0 * K; pAl = Al + (size_t)m0 * K;
        ar0 = tid >> 2;
        ar1 = (tid + 256) >> 2;
    }
    const __nv_bfloat16* pBh = Bh + (size_t)n0 * K;
    const __nv_bfloat16* pBl = Bl + (size_t)n0 * K;

    float acc[4][4][4];
    #pragma unroll
    for (int i = 0; i < 4; i++)
        #pragma unroll
        for (int j = 0; j < 4; j++)
            #pragma unroll
            for (int r = 0; r < 4; r++) acc[i][j][r] = 0.f;

    const int nk = K >> 5;   // K chunks of 32 (always >= 16 here)
    issue_stage(sbase,                 pAh, pAl, pBh, pBl, K, 0,  tid, ar0, ar1); CP_COMMIT();
    issue_stage(sbase + STG_BYTES,     pAh, pAl, pBh, pBl, K, 32, tid, ar0, ar1); CP_COMMIT();
    issue_stage(sbase + 2 * STG_BYTES, pAh, pAl, pBh, pBl, K, 64, tid, ar0, ar1); CP_COMMIT();

    int laneA_row = lane & 15;
    int laneA_k   = ((lane >> 4) & 1) * 8;
    int laneB_n   = ((lane >> 4) & 1) * 8 + (lane & 7);
    int laneB_k   = ((lane >> 3) & 1) * 8;

    int stg = 0;
    for (int kc = 0; kc < nk; kc++) {
        CP_WAIT2();
        __syncthreads();
        uint32_t sA = sbase + stg * STG_BYTES;
        uint32_t sAl_ = sA + TEN_BYTES, sBh_ = sA + 2 * TEN_BYTES, sBl_ = sA + 3 * TEN_BYTES;

        #pragma unroll
        for (int kk = 0; kk < 32; kk += 16) {
            uint32_t ah[4][4], al[4][4], bh[4][2], bl[4][2];
            #pragma unroll
            for (int mi = 0; mi < 4; mi++) {
                uint32_t off = (uint32_t)((wm + mi * 16 + laneA_row) * LDSH + kk + laneA_k) * 2;
                ldm_x4(ah[mi], sA + off);
                ldm_x4(al[mi], sAl_ + off);
            }
            #pragma unroll
            for (int j = 0; j < 2; j++) {
                uint32_t off = (uint32_t)((wn + j * 16 + laneB_n) * LDSH + kk + laneB_k) * 2;
                uint32_t rb[4];
                ldm_x4(rb, sBh_ + off);
                bh[2 * j][0] = rb[0]; bh[2 * j][1] = rb[1];
                bh[2 * j + 1][0] = rb[2]; bh[2 * j + 1][1] = rb[3];
                ldm_x4(rb, sBl_ + off);
                bl[2 * j][0] = rb[0]; bl[2 * j][1] = rb[1];
                bl[2 * j + 1][0] = rb[2]; bl[2 * j + 1][1] = rb[3];
            }
            #pragma unroll
            for (int mi = 0; mi < 4; mi++)
                #pragma unroll
                for (int ni = 0; ni < 4; ni++) {
                    mma_bf16(acc[mi][ni], ah[mi], bh[ni]);
                    mma_bf16(acc[mi][ni], ah[mi], bl[ni]);
                    mma_bf16(acc[mi][ni], al[mi], bh[ni]);
                }
        }
        __syncthreads();
        if (kc + 3 < nk)
            issue_stage(sbase + stg * STG_BYTES, pAh, pAl, pBh, pBl, K, (kc + 3) * 32, tid, ar0, ar1);
        CP_COMMIT();
        stg = (stg == 2) ? 0 : stg + 1;
    }

    int r0 = lane >> 2, c0 = (lane & 3) * 2;
    if (Hh) {
        // fused SwiGLU epilogue: cols are (y,g) interleaved -> h = silu(g)*y
        int halfN = N >> 1;
        Hh += (size_t)z * sDz; Hl += (size_t)z * sDz;
        #pragma unroll
        for (int mi = 0; mi < 4; mi++) {
            #pragma unroll
            for (int ni = 0; ni < 4; ni++) {
                int row = m0 + wm + mi * 16 + r0;
                int p = (n0 + wn + ni * 8 + c0) >> 1;
                float y0 = acc[mi][ni][0], gg0 = acc[mi][ni][1];
                float h0 = y0 * gg0 / (1.f + __expf(-gg0));
                float y1 = acc[mi][ni][2], gg1 = acc[mi][ni][3];
                float h1 = y1 * gg1 / (1.f + __expf(-gg1));
                __nv_bfloat16 h, l;
                split_f32(h0, h, l);
                Hh[(size_t)row * halfN + p] = h; Hl[(size_t)row * halfN + p] = l;
                split_f32(h1, h, l);
                Hh[(size_t)(row + 8) * halfN + p] = h; Hl[(size_t)(row + 8) * halfN + p] = l;
            }
        }
    } else {
        D += (size_t)z * sDz;
        #pragma unroll
        for (int mi = 0; mi < 4; mi++) {
            #pragma unroll
            for (int ni = 0; ni < 4; ni++) {
                int row = m0 + wm + mi * 16 + r0;
                int col = n0 + wn + ni * 8 + c0;
                *(float2*)(D + (size_t)row * N + col) = make_float2(acc[mi][ni][0], acc[mi][ni][1]);
                *(float2*)(D + (size_t)(row + 8) * N + col) = make_float2(acc[mi][ni][2], acc[mi][ni][3]);
            }
        }
    }
}

// ---------------- combine ----------------
__global__ __launch_bounds__(256) void combine_kernel(
    const float* __restrict__ oe, const int* __restrict__ slots,
    const float* __restrict__ wts, float* __restrict__ out) {
    int t = blockIdx.x;
    int c = threadIdx.x * 4;
    int sl[TOPK]; float ww[TOPK];
    #pragma unroll
    for (int k = 0; k < TOPK; k++) { sl[k] = slots[t * TOPK + k]; ww[k] = wts[t * TOPK + k]; }
    float4 acc = *(float4*)(out + (size_t)t * CDIM + c);
    #pragma unroll
    for (int k = 0; k < TOPK; k++) {
        float4 v = *(const float4*)(oe + (size_t)sl[k] * CDIM + c);
        acc.x += ww[k] * v.x; acc.y += ww[k] * v.y;
        acc.z += ww[k] * v.z; acc.w += ww[k] * v.w;
    }
    *(float4*)(out + (size_t)t * CDIM + c) = acc;
}

// ---------------- launch ----------------
extern "C" void kernel_launch(void* const* d_in, const int* in_sizes, int n_in,
                              void* d_out, int out_size) {
    const float* x       = (const float*)d_in[0];
    const float* rw      = (const float*)d_in[1];
    const float* bias    = (const float*)d_in[2];
    const float* sup_w   = (const float*)d_in[3];
    const float* sdown_w = (const float*)d_in[4];
    const float* eup_w   = (const float*)d_in[5];
    const float* edown_w = (const float*)d_in[6];
    float* out = (float*)d_out;
    (void)in_sizes; (void)n_in; (void)out_size;

    __nv_bfloat16 *xh, *xl, *shh, *shl, *ehh, *ehl;
    __nv_bfloat16 *supt_h, *supt_l, *sdnt_h, *sdnt_l, *eupt_h, *eupt_l, *ednt_h, *ednt_l;
    float *eoe, *wts;
    int *counts, *rowidx, *slots;
    cudaGetSymbolAddress((void**)&xh, g_xh);       cudaGetSymbolAddress((void**)&xl, g_xl);
    cudaGetSymbolAddress((void**)&shh, g_shh);     cudaGetSymbolAddress((void**)&shl, g_shl);
    cudaGetSymbolAddress((void**)&ehh, g_ehh);     cudaGetSymbolAddress((void**)&ehl, g_ehl);
    cudaGetSymbolAddress((void**)&eoe, g_eoe);
    cudaGetSymbolAddress((void**)&supt_h, g_supt_h); cudaGetSymbolAddress((void**)&supt_l, g_supt_l);
    cudaGetSymbolAddress((void**)&sdnt_h, g_sdnt_h); cudaGetSymbolAddress((void**)&sdnt_l, g_sdnt_l);
    cudaGetSymbolAddress((void**)&eupt_h, g_eupt_h); cudaGetSymbolAddress((void**)&eupt_l, g_eupt_l);
    cudaGetSymbolAddress((void**)&ednt_h, g_ednt_h); cudaGetSymbolAddress((void**)&ednt_l, g_ednt_l);
    cudaGetSymbolAddress((void**)&counts, g_counts);
    cudaGetSymbolAddress((void**)&rowidx, g_rowidx);
    cudaGetSymbolAddress((void**)&slots, g_slots);
    cudaGetSymbolAddress((void**)&wts, g_wts);

    cudaFuncSetAttribute(gemm_kernel, cudaFuncAttributeMaxDynamicSharedMemorySize, 3 * STG_BYTES);
    const int gsmem = 3 * STG_BYTES;

    // 1. routing (also writes xh/xl + rowidx)
    zero_counts_kernel<<<1, 64>>>(counts);
    router_kernel<<<NTOK, 256>>>(x, rw, bias, counts, rowidx, slots, wts, xh, xl);

    // 2. weight prep (transpose + split; up weights (y,g)-interleaved)
    transpose_split_kernel<<<dim3(2 * HS / 32, CDIM / 32, 1), dim3(32, 8)>>>(
        sup_w, supt_h, supt_l, CDIM, 2 * HS, 0, 0, HS);
    transpose_split_kernel<<<dim3(CDIM / 32, HS / 32, 1), dim3(32, 8)>>>(
        sdown_w, sdnt_h, sdnt_l, HS, CDIM, 0, 0, 0);
    transpose_split_kernel<<<dim3(2 * HE / 32, CDIM / 32, NEXP), dim3(32, 8)>>>(
        eup_w, eupt_h, eupt_l, CDIM, 2 * HE, (long)CDIM * 2 * HE, (long)2 * HE * CDIM, HE);
    transpose_split_kernel<<<dim3(CDIM / 32, HE / 32, NEXP), dim3(32, 8)>>>(
        edown_w, ednt_h, ednt_l, HE, CDIM, (long)HE * CDIM, (long)CDIM * HE, 0);

    // 3. shared expert: up(+swiglu fused) -> down
    gemm_kernel<<<dim3(2 * HS / 128, NTOK / 128, 1), 256, gsmem>>>(
        xh, xl, supt_h, supt_l, nullptr, shh, shl, NTOK, 2 * HS, CDIM, 0, 0, 0, nullptr, nullptr);
    gemm_kernel<<<dim3(CDIM / 128, NTOK / 128, 1), 256, gsmem>>>(
        shh, shl, sdnt_h, sdnt_l, out, nullptr, nullptr, NTOK, CDIM, HS, 0, 0, 0, nullptr, nullptr);

    // 4. expert grouped GEMMs: up(gather A + swiglu fused) -> down
    gemm_kernel<<<dim3(2 * HE / 128, CAP / 128, NEXP), 256, gsmem>>>(
        xh, xl, eupt_h, eupt_l, nullptr, ehh, ehl, CAP, 2 * HE, CDIM,
        0, (long)(2 * HE) * CDIM, (long)CAP * HE, counts, rowidx);
    gemm_kernel<<<dim3(CDIM / 128, CAP / 128, NEXP), 256, gsmem>>>(
        ehh, ehl, ednt_h, ednt_l, eoe, nullptr, nullptr, CAP, CDIM, HE,
        (long)CAP * HE, (long)CDIM * HE, (long)CAP * CDIM, counts, nullptr);

    // 5. combine
    combine_kernel<<<NTOK, 256>>>(eoe, slots, wts, out);
}

// round 5
// speedup vs baseline: 2.8569x; 1.2967x over previous
#include <cuda_runtime.h>
#include <cuda_bf16.h>
#include <cstdint>

// ---------------- shapes ----------------
#define NTOK 4096
#define CDIM 1024
#define NEXP 64
#define TOPK 8
#define CAP  1024
#define HS   1024
#define HE   512

// ---------------- helpers ----------------
__device__ __forceinline__ uint32_t smem_u32(const void* p) {
    uint32_t a;
    asm("{ .reg .u64 t; cvta.to.shared.u64 t, %1; cvt.u32.u64 %0, t; }" : "=r"(a) : "l"(p));
    return a;
}
#define CP_ASYNC16(dst, src) \
    asm volatile("cp.async.cg.shared.global [%0], [%1], 16;" :: "r"(dst), "l"(src))
#define CP_COMMIT() asm volatile("cp.async.commit_group;" ::: "memory")
#define CP_WAIT2()  asm volatile("cp.async.wait_group 2;" ::: "memory")

__device__ __forceinline__ void ldm_x4(uint32_t* r, uint32_t addr) {
    asm volatile("ldmatrix.sync.aligned.m8n8.x4.shared.b16 {%0,%1,%2,%3}, [%4];"
        : "=r"(r[0]), "=r"(r[1]), "=r"(r[2]), "=r"(r[3]) : "r"(addr));
}
__device__ __forceinline__ void mma_tf32(float* d, const uint32_t* a, const uint32_t* b) {
    asm volatile(
        "mma.sync.aligned.m16n8k8.row.col.f32.tf32.tf32.f32 "
        "{%0,%1,%2,%3}, {%4,%5,%6,%7}, {%8,%9}, {%0,%1,%2,%3};"
        : "+f"(d[0]), "+f"(d[1]), "+f"(d[2]), "+f"(d[3])
        : "r"(a[0]), "r"(a[1]), "r"(a[2]), "r"(a[3]), "r"(b[0]), "r"(b[1]));
}
__device__ __forceinline__ float to_tf32(float v) {
    uint32_t r;
    asm("cvt.rna.tf32.f32 %0, %1;" : "=r"(r) : "f"(v));
    return __uint_as_float(r);
}

// ---------------- scratch (device globals) ----------------
__device__ float g_xr  [(size_t)NTOK * CDIM];
__device__ float g_sh  [(size_t)NTOK * HS];
__device__ float g_eh  [(size_t)NEXP * CAP * HE];
__device__ float g_eoe [(size_t)NEXP * CAP * CDIM];
__device__ float g_supt[(size_t)(2 * HS) * CDIM];
__device__ float g_sdnt[(size_t)CDIM * HS];
__device__ float g_eupt[(size_t)NEXP * (2 * HE) * CDIM];
__device__ float g_ednt[(size_t)NEXP * CDIM * HE];
__device__ int   g_counts[NEXP];
__device__ int   g_rowidx[NEXP * CAP];
__device__ int   g_slots[NTOK * TOPK];
__device__ float g_wts [NTOK * TOPK];

// ---------------- small kernels ----------------
__global__ void zero_counts_kernel(int* counts) {
    if (threadIdx.x < NEXP) counts[threadIdx.x] = 0;
}

// transpose + tf32-round: in [K][N] fp32 -> out [N][K] fp32(tf32).
// If half>0, output rows (y,g)-interleaved: n<half -> 2n ; else 2(n-half)+1.
__global__ void transpose_round_kernel(const float* __restrict__ in, float* __restrict__ o,
                                       int K, int N, long inz, long outz, int half) {
    __shared__ float tile[32][33];
    int z = blockIdx.z;
    in += (size_t)z * inz; o += (size_t)z * outz;
    int n0 = blockIdx.x * 32, k0 = blockIdx.y * 32;
    int tx = threadIdx.x, ty = threadIdx.y;
    #pragma unroll
    for (int i = 0; i < 32; i += 8)
        tile[ty + i][tx] = in[(size_t)(k0 + ty + i) * N + n0 + tx];
    __syncthreads();
    #pragma unroll
    for (int i = 0; i < 32; i += 8) {
        float v = tile[tx][ty + i];
        int n = n0 + ty + i;
        int nout = (half > 0) ? ((n < half) ? 2 * n : 2 * (n - half) + 1) : n;
        o[(size_t)nout * K + k0 + tx] = to_tf32(v);
    }
}

// ---------------- router: scores, top-8, slot assign, write xr + rowidx ----------------
__global__ __launch_bounds__(256) void router_kernel(
    const float* __restrict__ x, const float* __restrict__ rw, const float* __restrict__ bias,
    int* __restrict__ counts, int* __restrict__ rowidx,
    int* __restrict__ slots, float* __restrict__ wts, float* __restrict__ xr) {
    int t = blockIdx.x;
    int tid = threadIdx.x;
    __shared__ float xs[CDIM];
    __shared__ float partial[256];
    __shared__ float sc[NEXP];
    __shared__ float sb[NEXP];

    for (int i = tid; i < CDIM; i += 256) xs[i] = x[(size_t)t * CDIM + i];
    __syncthreads();

    int e = tid & 63, part = tid >> 6;
    float acc = 0.f;
    const float* rwp = rw + (size_t)(part * 256) * NEXP + e;
    #pragma unroll 8
    for (int c = 0; c < 256; c++) acc += xs[part * 256 + c] * rwp[(size_t)c * NEXP];
    partial[tid] = acc;
    __syncthreads();
    if (tid < NEXP) {
        float v = partial[tid] + partial[tid + 64] + partial[tid + 128] + partial[tid + 192];
        float s = 1.f / (1.f + __expf(-v));
        sc[tid] = s;
        sb[tid] = s + bias[tid];
    }
    __syncthreads();

    if (tid == 0) {
        float wsum = 0.f;
        int eid[TOPK]; float ww[TOPK];
        #pragma unroll
        for (int k = 0; k < TOPK; k++) {
            int best = 0; float bv = sb[0];
            for (int i = 1; i < NEXP; i++) { float v = sb[i]; if (v > bv) { bv = v; best = i; } }
            sb[best] = -1e30f;
            eid[k] = best; ww[k] = sc[best]; wsum += sc[best];
        }
        float inv = 1.f / wsum;
        #pragma unroll
        for (int k = 0; k < TOPK; k++) {
            int pos  = atomicAdd(&counts[eid[k]], 1);
            int slot = eid[k] * CAP + pos;
            rowidx[slot] = t;
            slots[t * TOPK + k] = slot;
            wts  [t * TOPK + k] = ww[k] * inv;
        }
    }

    for (int i = tid; i < CDIM; i += 256)
        xr[(size_t)t * CDIM + i] = to_tf32(xs[i]);
}

// ---------------- tf32 mma.sync GEMM: D[M,N] = A[M,K] @ Bt[N,K]^T ----------------
// CTA tile 128x128, Kc=32 floats, 3-stage cp.async pipeline.
// Smem per tensor tile: 128 rows x 36 floats = 18432 B; stage = 36864 B.
#define LDSF 36
#define ROWB 144
#define TEN_BYTES 18432
#define STG_BYTES 36864

__device__ __forceinline__ void issue_stage(
    uint32_t sdst, const float* __restrict__ pA, const float* __restrict__ pB,
    int K, int kcol, int tid, const int* ar) {
    #pragma unroll
    for (int i = 0; i < 4; i++) {
        int id = tid + 256 * i;
        int row = id >> 3, c4 = id & 7;
        uint32_t so = (uint32_t)(row * ROWB + c4 * 16);
        CP_ASYNC16(sdst + so, pA + (size_t)ar[i] * K + kcol + c4 * 4);
        CP_ASYNC16(sdst + TEN_BYTES + so, pB + (size_t)row * K + kcol + c4 * 4);
    }
}

__global__ __launch_bounds__(256, 1) void gemm_kernel(
    const float* __restrict__ A, const float* __restrict__ B,
    float* __restrict__ D, float* __restrict__ H,
    int M, int N, int K,
    long sAz, long sBz, long sDz,
    const int* __restrict__ counts, const int* __restrict__ rowidx) {
    extern __shared__ __align__(128) char smem[];
    int z = blockIdx.z;
    if (counts) M = counts[z];
    int m0 = blockIdx.y * 128;
    if (m0 >= M) return;
    int n0 = blockIdx.x * 128;
    A += (size_t)z * sAz; B += (size_t)z * sBz;

    int tid = threadIdx.x, wid = tid >> 5, lane = tid & 31;
    int wm = (wid & 1) * 64;
    int wn = (wid >> 1) * 32;
    uint32_t sbase = smem_u32(smem);

    const float* pA;
    int ar[4];
    if (rowidx) {
        const int* ridx = rowidx + (size_t)z * CAP + m0;
        pA = A;
        #pragma unroll
        for (int i = 0; i < 4; i++) ar[i] = ridx[(tid >> 3) + 32 * i];
    } else {
        pA = A + (size_t)m0 * K;
        #pragma unroll
        for (int i = 0; i < 4; i++) ar[i] = (tid >> 3) + 32 * i;
    }
    const float* pB = B + (size_t)n0 * K;

    float acc[4][4][4];
    #pragma unroll
    for (int i = 0; i < 4; i++)
        #pragma unroll
        for (int j = 0; j < 4; j++)
            #pragma unroll
            for (int r = 0; r < 4; r++) acc[i][j][r] = 0.f;

    const int nk = K >> 5;
    issue_stage(sbase,                 pA, pB, K, 0,  tid, ar); CP_COMMIT();
    issue_stage(sbase + STG_BYTES,     pA, pB, K, 32, tid, ar); CP_COMMIT();
    issue_stage(sbase + 2 * STG_BYTES, pA, pB, K, 64, tid, ar); CP_COMMIT();

    int laneA_row = lane & 15;
    int laneA_c   = ((lane >> 4) & 1) * 16;
    int laneB_n   = (lane & 7) + ((lane >> 4) & 1) * 8;
    int laneB_c   = ((lane >> 3) & 1) * 16;

    int stg = 0;
    for (int kc = 0; kc < nk; kc++) {
        CP_WAIT2();
        __syncthreads();
        uint32_t sA = sbase + stg * STG_BYTES;
        uint32_t sB = sA + TEN_BYTES;

        #pragma unroll
        for (int s = 0; s < 4; s++) {
            uint32_t a[4][4], b[4][2];
            #pragma unroll
            for (int mi = 0; mi < 4; mi++)
                ldm_x4(a[mi], sA + (uint32_t)((wm + mi * 16 + laneA_row) * ROWB + s * 32 + laneA_c));
            #pragma unroll
            for (int j = 0; j < 2; j++) {
                uint32_t rb[4];
                ldm_x4(rb, sB + (uint32_t)((wn + j * 16 + laneB_n) * ROWB + s * 32 + laneB_c));
                b[2 * j][0] = rb[0]; b[2 * j][1] = rb[1];
                b[2 * j + 1][0] = rb[2]; b[2 * j + 1][1] = rb[3];
            }
            #pragma unroll
            for (int mi = 0; mi < 4; mi++)
                #pragma unroll
                for (int ni = 0; ni < 4; ni++)
                    mma_tf32(acc[mi][ni], a[mi], b[ni]);
        }
        __syncthreads();
        if (kc + 3 < nk)
            issue_stage(sbase + stg * STG_BYTES, pA, pB, K, (kc + 3) * 32, tid, ar);
        CP_COMMIT();
        stg = (stg == 2) ? 0 : stg + 1;
    }

    int r0 = lane >> 2, c0 = (lane & 3) * 2;
    if (H) {
        // fused SwiGLU epilogue: cols (y,g) interleaved -> h = silu(g)*y, tf32-rounded
        int halfN = N >> 1;
        H += (size_t)z * sDz;
        #pragma unroll
        for (int mi = 0; mi < 4; mi++) {
            #pragma unroll
            for (int ni = 0; ni < 4; ni++) {
                int row = m0 + wm + mi * 16 + r0;
                int p = (n0 + wn + ni * 8 + c0) >> 1;
                float y0 = acc[mi][ni][0], gg0 = acc[mi][ni][1];
                float y1 = acc[mi][ni][2], gg1 = acc[mi][ni][3];
                H[(size_t)row * halfN + p]       = to_tf32(y0 * gg0 / (1.f + __expf(-gg0)));
                H[(size_t)(row + 8) * halfN + p] = to_tf32(y1 * gg1 / (1.f + __expf(-gg1)));
            }
        }
    } else {
        D += (size_t)z * sDz;
        #pragma unroll
        for (int mi = 0; mi < 4; mi++) {
            #pragma unroll
            for (int ni = 0; ni < 4; ni++) {
                int row = m0 + wm + mi * 16 + r0;
                int col = n0 + wn + ni * 8 + c0;
                *(float2*)(D + (size_t)row * N + col) = make_float2(acc[mi][ni][0], acc[mi][ni][1]);
                *(float2*)(D + (size_t)(row + 8) * N + col) = make_float2(acc[mi][ni][2], acc[mi][ni][3]);
            }
        }
    }
}

// ---------------- combine ----------------
__global__ __launch_bounds__(256) void combine_kernel(
    const float* __restrict__ oe, const int* __restrict__ slots,
    const float* __restrict__ wts, float* __restrict__ out) {
    int t = blockIdx.x;
    int c = threadIdx.x * 4;
    int sl[TOPK]; float ww[TOPK];
    #pragma unroll
    for (int k = 0; k < TOPK; k++) { sl[k] = slots[t * TOPK + k]; ww[k] = wts[t * TOPK + k]; }
    float4 acc = *(float4*)(out + (size_t)t * CDIM + c);
    #pragma unroll
    for (int k = 0; k < TOPK; k++) {
        float4 v = *(const float4*)(oe + (size_t)sl[k] * CDIM + c);
        acc.x += ww[k] * v.x; acc.y += ww[k] * v.y;
        acc.z += ww[k] * v.z; acc.w += ww[k] * v.w;
    }
    *(float4*)(out + (size_t)t * CDIM + c) = acc;
}

// ---------------- launch ----------------
extern "C" void kernel_launch(void* const* d_in, const int* in_sizes, int n_in,
                              void* d_out, int out_size) {
    const float* x       = (const float*)d_in[0];
    const float* rw      = (const float*)d_in[1];
    const float* bias    = (const float*)d_in[2];
    const float* sup_w   = (const float*)d_in[3];
    const float* sdown_w = (const float*)d_in[4];
    const float* eup_w   = (const float*)d_in[5];
    const float* edown_w = (const float*)d_in[6];
    float* out = (float*)d_out;
    (void)in_sizes; (void)n_in; (void)out_size;

    float *xr, *sh, *eh, *eoe, *supt, *sdnt, *eupt, *ednt, *wts;
    int *counts, *rowidx, *slots;
    cudaGetSymbolAddress((void**)&xr, g_xr);
    cudaGetSymbolAddress((void**)&sh, g_sh);
    cudaGetSymbolAddress((void**)&eh, g_eh);
    cudaGetSymbolAddress((void**)&eoe, g_eoe);
    cudaGetSymbolAddress((void**)&supt, g_supt);
    cudaGetSymbolAddress((void**)&sdnt, g_sdnt);
    cudaGetSymbolAddress((void**)&eupt, g_eupt);
    cudaGetSymbolAddress((void**)&ednt, g_ednt);
    cudaGetSymbolAddress((void**)&counts, g_counts);
    cudaGetSymbolAddress((void**)&rowidx, g_rowidx);
    cudaGetSymbolAddress((void**)&slots, g_slots);
    cudaGetSymbolAddress((void**)&wts, g_wts);

    cudaFuncSetAttribute(gemm_kernel, cudaFuncAttributeMaxDynamicSharedMemorySize, 3 * STG_BYTES);
    const int gsmem = 3 * STG_BYTES;

    // 1. routing (writes xr + rowidx)
    zero_counts_kernel<<<1, 64>>>(counts);
    router_kernel<<<NTOK, 256>>>(x, rw, bias, counts, rowidx, slots, wts, xr);

    // 2. weight prep (transpose + tf32 round; up weights (y,g)-interleaved)
    transpose_round_kernel<<<dim3(2 * HS / 32, CDIM / 32, 1), dim3(32, 8)>>>(
        sup_w, supt, CDIM, 2 * HS, 0, 0, HS);
    transpose_round_kernel<<<dim3(CDIM / 32, HS / 32, 1), dim3(32, 8)>>>(
        sdown_w, sdnt, HS, CDIM, 0, 0, 0);
    transpose_round_kernel<<<dim3(2 * HE / 32, CDIM / 32, NEXP), dim3(32, 8)>>>(
        eup_w, eupt, CDIM, 2 * HE, (long)CDIM * 2 * HE, (long)2 * HE * CDIM, HE);
    transpose_round_kernel<<<dim3(CDIM / 32, HE / 32, NEXP), dim3(32, 8)>>>(
        edown_w, ednt, HE, CDIM, (long)HE * CDIM, (long)CDIM * HE, 0);

    // 3. shared expert: up(+swiglu fused) -> down
    gemm_kernel<<<dim3(2 * HS / 128, NTOK / 128, 1), 256, gsmem>>>(
        xr, supt, nullptr, sh, NTOK, 2 * HS, CDIM, 0, 0, 0, nullptr, nullptr);
    gemm_kernel<<<dim3(CDIM / 128, NTOK / 128, 1), 256, gsmem>>>(
        sh, sdnt, out, nullptr, NTOK, CDIM, HS, 0, 0, 0, nullptr, nullptr);

    // 4. expert grouped GEMMs: up(gather A + swiglu fused) -> down
    gemm_kernel<<<dim3(2 * HE / 128, CAP / 128, NEXP), 256, gsmem>>>(
        xr, eupt, nullptr, eh, CAP, 2 * HE, CDIM,
        0, (long)(2 * HE) * CDIM, (long)CAP * HE, counts, rowidx);
    gemm_kernel<<<dim3(CDIM / 128, CAP / 128, NEXP), 256, gsmem>>>(
        eh, ednt, eoe, nullptr, CAP, CDIM, HE,
        (long)CAP * HE, (long)CDIM * HE, (long)CAP * CDIM, counts, nullptr);

    // 5. combine
    combine_kernel<<<NTOK, 256>>>(eoe, slots, wts, out);
}

// round 6
// speedup vs baseline: 3.1950x; 1.1184x over previous
#include <cuda_runtime.h>
#include <cuda_bf16.h>
#include <cstdint>

// ---------------- shapes ----------------
#define NTOK 4096
#define CDIM 1024
#define NEXP 64
#define TOPK 8
#define CAP  1024
#define HS   1024
#define HE   512

// ---------------- helpers ----------------
__device__ __forceinline__ uint32_t smem_u32(const void* p) {
    uint32_t a;
    asm("{ .reg .u64 t; cvta.to.shared.u64 t, %1; cvt.u32.u64 %0, t; }" : "=r"(a) : "l"(p));
    return a;
}
#define CP_ASYNC16(dst, src) \
    asm volatile("cp.async.cg.shared.global [%0], [%1], 16;" :: "r"(dst), "l"(src))
#define CP_COMMIT() asm volatile("cp.async.commit_group;" ::: "memory")
#define CP_WAIT2()  asm volatile("cp.async.wait_group 2;" ::: "memory")

__device__ __forceinline__ void ldm_x4(uint32_t* r, uint32_t addr) {
    asm volatile("ldmatrix.sync.aligned.m8n8.x4.shared.b16 {%0,%1,%2,%3}, [%4];"
        : "=r"(r[0]), "=r"(r[1]), "=r"(r[2]), "=r"(r[3]) : "r"(addr));
}
__device__ __forceinline__ void mma_tf32(float* d, const uint32_t* a, const uint32_t* b) {
    asm volatile(
        "mma.sync.aligned.m16n8k8.row.col.f32.tf32.tf32.f32 "
        "{%0,%1,%2,%3}, {%4,%5,%6,%7}, {%8,%9}, {%0,%1,%2,%3};"
        : "+f"(d[0]), "+f"(d[1]), "+f"(d[2]), "+f"(d[3])
        : "r"(a[0]), "r"(a[1]), "r"(a[2]), "r"(a[3]), "r"(b[0]), "r"(b[1]));
}
__device__ __forceinline__ float to_tf32(float v) {
    uint32_t r;
    asm("cvt.rna.tf32.f32 %0, %1;" : "=r"(r) : "f"(v));
    return __uint_as_float(r);
}

// ---------------- scratch (device globals) ----------------
__device__ float g_xr  [(size_t)NTOK * CDIM];
__device__ float g_sh  [(size_t)NTOK * HS];
__device__ float g_eh  [(size_t)NEXP * CAP * HE];
__device__ float g_eoe [(size_t)NEXP * CAP * CDIM];
__device__ float g_supt[(size_t)(2 * HS) * CDIM];
__device__ float g_sdnt[(size_t)CDIM * HS];
__device__ float g_eupt[(size_t)NEXP * (2 * HE) * CDIM];
__device__ float g_ednt[(size_t)NEXP * CDIM * HE];
__device__ int   g_counts[NEXP];
__device__ int   g_rowidx[NEXP * CAP];
__device__ int   g_slots[NTOK * TOPK];
__device__ float g_wts [NTOK * TOPK];

// ---------------- small kernels ----------------
__global__ void zero_counts_kernel(int* counts) {
    if (threadIdx.x < NEXP) counts[threadIdx.x] = 0;
}

// transpose + tf32-round: in [K][N] fp32 -> out [N][K] fp32(tf32).
// If half>0, output rows (y,g)-interleaved: n<half -> 2n ; else 2(n-half)+1.
__global__ void transpose_round_kernel(const float* __restrict__ in, float* __restrict__ o,
                                       int K, int N, long inz, long outz, int half) {
    __shared__ float tile[32][33];
    int z = blockIdx.z;
    in += (size_t)z * inz; o += (size_t)z * outz;
    int n0 = blockIdx.x * 32, k0 = blockIdx.y * 32;
    int tx = threadIdx.x, ty = threadIdx.y;
    #pragma unroll
    for (int i = 0; i < 32; i += 8)
        tile[ty + i][tx] = in[(size_t)(k0 + ty + i) * N + n0 + tx];
    __syncthreads();
    #pragma unroll
    for (int i = 0; i < 32; i += 8) {
        float v = tile[tx][ty + i];
        int n = n0 + ty + i;
        int nout = (half > 0) ? ((n < half) ? 2 * n : 2 * (n - half) + 1) : n;
        o[(size_t)nout * K + k0 + tx] = to_tf32(v);
    }
}

// ---------------- router ----------------
__global__ __launch_bounds__(256) void router_kernel(
    const float* __restrict__ x, const float* __restrict__ rw, const float* __restrict__ bias,
    int* __restrict__ counts, int* __restrict__ rowidx,
    int* __restrict__ slots, float* __restrict__ wts, float* __restrict__ xr) {
    int t = blockIdx.x;
    int tid = threadIdx.x;
    __shared__ float xs[CDIM];
    __shared__ float partial[256];
    __shared__ float sc[NEXP];
    __shared__ float sb[NEXP];

    for (int i = tid; i < CDIM; i += 256) xs[i] = x[(size_t)t * CDIM + i];
    __syncthreads();

    int e = tid & 63, part = tid >> 6;
    float acc = 0.f;
    const float* rwp = rw + (size_t)(part * 256) * NEXP + e;
    #pragma unroll 8
    for (int c = 0; c < 256; c++) acc += xs[part * 256 + c] * rwp[(size_t)c * NEXP];
    partial[tid] = acc;
    __syncthreads();
    if (tid < NEXP) {
        float v = partial[tid] + partial[tid + 64] + partial[tid + 128] + partial[tid + 192];
        float s = 1.f / (1.f + __expf(-v));
        sc[tid] = s;
        sb[tid] = s + bias[tid];
    }
    __syncthreads();

    if (tid == 0) {
        float wsum = 0.f;
        int eid[TOPK]; float ww[TOPK];
        #pragma unroll
        for (int k = 0; k < TOPK; k++) {
            int best = 0; float bv = sb[0];
            for (int i = 1; i < NEXP; i++) { float v = sb[i]; if (v > bv) { bv = v; best = i; } }
            sb[best] = -1e30f;
            eid[k] = best; ww[k] = sc[best]; wsum += sc[best];
        }
        float inv = 1.f / wsum;
        #pragma unroll
        for (int k = 0; k < TOPK; k++) {
            int pos  = atomicAdd(&counts[eid[k]], 1);
            int slot = eid[k] * CAP + pos;
            rowidx[slot] = t;
            slots[t * TOPK + k] = slot;
            wts  [t * TOPK + k] = ww[k] * inv;
        }
    }

    for (int i = tid; i < CDIM; i += 256)
        xr[(size_t)t * CDIM + i] = to_tf32(xs[i]);
}

// ---------------- tf32 mma.sync GEMM: D[M,N] = A[M,K] @ Bt[N,K]^T ----------------
// CTA tile 128Mx256N, 8 warps of 64x64, Kc=32, 3-stage cp.async pipeline.
// Smem: A 128x144B = 18432, B 256x144B = 36864; stage = 55296; 3 stages = 165888.
#define ROWB 144
#define A_BYTES 18432
#define STG_BYTES 55296

__device__ __forceinline__ void issue_stage(
    uint32_t sdst, const float* __restrict__ pA, const float* __restrict__ pB,
    int K, int kcol, int tid, const int* ar) {
    #pragma unroll
    for (int i = 0; i < 4; i++) {
        int id = tid + 256 * i;
        int row = id >> 3, c4 = id & 7;
        uint32_t so = (uint32_t)(row * ROWB + c4 * 16);
        CP_ASYNC16(sdst + so, pA + (size_t)ar[i] * K + kcol + c4 * 4);
    }
    #pragma unroll
    for (int i = 0; i < 8; i++) {
        int id = tid + 256 * i;
        int row = id >> 3, c4 = id & 7;
        uint32_t so = (uint32_t)(row * ROWB + c4 * 16);
        CP_ASYNC16(sdst + A_BYTES + so, pB + (size_t)row * K + kcol + c4 * 4);
    }
}

__global__ __launch_bounds__(256, 1) void gemm_kernel(
    const float* __restrict__ A, const float* __restrict__ B,
    float* __restrict__ D, float* __restrict__ H,
    int M, int N, int K,
    long sAz, long sBz, long sDz,
    const int* __restrict__ counts, const int* __restrict__ rowidx) {
    extern __shared__ __align__(128) char smem[];
    int z = blockIdx.z;
    if (counts) M = counts[z];
    int m0 = blockIdx.y * 128;
    if (m0 >= M) return;
    int n0 = blockIdx.x * 256;
    A += (size_t)z * sAz; B += (size_t)z * sBz;

    int tid = threadIdx.x, wid = tid >> 5, lane = tid & 31;
    int wm = (wid & 1) * 64;
    int wn = (wid >> 1) * 64;
    uint32_t sbase = smem_u32(smem);

    const float* pA;
    int ar[4];
    if (rowidx) {
        const int* ridx = rowidx + (size_t)z * CAP + m0;
        pA = A;
        #pragma unroll
        for (int i = 0; i < 4; i++) ar[i] = ridx[(tid >> 3) + 32 * i];
    } else {
        pA = A + (size_t)m0 * K;
        #pragma unroll
        for (int i = 0; i < 4; i++) ar[i] = (tid >> 3) + 32 * i;
    }
    const float* pB = B + (size_t)n0 * K;

    float acc[4][8][4];
    #pragma unroll
    for (int i = 0; i < 4; i++)
        #pragma unroll
        for (int j = 0; j < 8; j++)
            #pragma unroll
            for (int r = 0; r < 4; r++) acc[i][j][r] = 0.f;

    const int nk = K >> 5;
    issue_stage(sbase,                 pA, pB, K, 0,  tid, ar); CP_COMMIT();
    issue_stage(sbase + STG_BYTES,     pA, pB, K, 32, tid, ar); CP_COMMIT();
    issue_stage(sbase + 2 * STG_BYTES, pA, pB, K, 64, tid, ar); CP_COMMIT();

    int laneA_row = lane & 15;
    int laneA_c   = ((lane >> 4) & 1) * 16;
    int laneB_n   = (lane & 7) + ((lane >> 4) & 1) * 8;
    int laneB_c   = ((lane >> 3) & 1) * 16;

    int stg = 0;
    for (int kc = 0; kc < nk; kc++) {
        CP_WAIT2();
        __syncthreads();
        uint32_t sA = sbase + stg * STG_BYTES;
        uint32_t sB = sA + A_BYTES;

        #pragma unroll
        for (int s = 0; s < 4; s++) {
            uint32_t a[4][4];
            #pragma unroll
            for (int mi = 0; mi < 4; mi++)
                ldm_x4(a[mi], sA + (uint32_t)((wm + mi * 16 + laneA_row) * ROWB + s * 32 + laneA_c));
            #pragma unroll
            for (int j = 0; j < 4; j++) {
                uint32_t rb[4];
                ldm_x4(rb, sB + (uint32_t)((wn + j * 16 + laneB_n) * ROWB + s * 32 + laneB_c));
                #pragma unroll
                for (int mi = 0; mi < 4; mi++) {
                    mma_tf32(acc[mi][2 * j],     a[mi], rb);
                    mma_tf32(acc[mi][2 * j + 1], a[mi], rb + 2);
                }
            }
        }
        __syncthreads();
        if (kc + 3 < nk)
            issue_stage(sbase + stg * STG_BYTES, pA, pB, K, (kc + 3) * 32, tid, ar);
        CP_COMMIT();
        stg = (stg == 2) ? 0 : stg + 1;
    }

    int r0 = lane >> 2, c0 = (lane & 3) * 2;
    if (H) {
        // fused SwiGLU epilogue: cols (y,g) interleaved -> h = silu(g)*y, tf32-rounded
        int halfN = N >> 1;
        H += (size_t)z * sDz;
        #pragma unroll
        for (int mi = 0; mi < 4; mi++) {
            #pragma unroll
            for (int ni = 0; ni < 8; ni++) {
                int row = m0 + wm + mi * 16 + r0;
                int p = (n0 + wn + ni * 8 + c0) >> 1;
                float y0 = acc[mi][ni][0], gg0 = acc[mi][ni][1];
                float y1 = acc[mi][ni][2], gg1 = acc[mi][ni][3];
                H[(size_t)row * halfN + p]       = to_tf32(y0 * gg0 / (1.f + __expf(-gg0)));
                H[(size_t)(row + 8) * halfN + p] = to_tf32(y1 * gg1 / (1.f + __expf(-gg1)));
            }
        }
    } else {
        D += (size_t)z * sDz;
        #pragma unroll
        for (int mi = 0; mi < 4; mi++) {
            #pragma unroll
            for (int ni = 0; ni < 8; ni++) {
                int row = m0 + wm + mi * 16 + r0;
                int col = n0 + wn + ni * 8 + c0;
                *(float2*)(D + (size_t)row * N + col) = make_float2(acc[mi][ni][0], acc[mi][ni][1]);
                *(float2*)(D + (size_t)(row + 8) * N + col) = make_float2(acc[mi][ni][2], acc[mi][ni][3]);
            }
        }
    }
}

// ---------------- combine ----------------
__global__ __launch_bounds__(256) void combine_kernel(
    const float* __restrict__ oe, const int* __restrict__ slots,
    const float* __restrict__ wts, float* __restrict__ out) {
    int t = blockIdx.x;
    int c = threadIdx.x * 4;
    int sl[TOPK]; float ww[TOPK];
    #pragma unroll
    for (int k = 0; k < TOPK; k++) { sl[k] = slots[t * TOPK + k]; ww[k] = wts[t * TOPK + k]; }
    float4 acc = *(float4*)(out + (size_t)t * CDIM + c);
    #pragma unroll
    for (int k = 0; k < TOPK; k++) {
        float4 v = *(const float4*)(oe + (size_t)sl[k] * CDIM + c);
        acc.x += ww[k] * v.x; acc.y += ww[k] * v.y;
        acc.z += ww[k] * v.z; acc.w += ww[k] * v.w;
    }
    *(float4*)(out + (size_t)t * CDIM + c) = acc;
}

// ---------------- launch ----------------
extern "C" void kernel_launch(void* const* d_in, const int* in_sizes, int n_in,
                              void* d_out, int out_size) {
    const float* x       = (const float*)d_in[0];
    const float* rw      = (const float*)d_in[1];
    const float* bias    = (const float*)d_in[2];
    const float* sup_w   = (const float*)d_in[3];
    const float* sdown_w = (const float*)d_in[4];
    const float* eup_w   = (const float*)d_in[5];
    const float* edown_w = (const float*)d_in[6];
    float* out = (float*)d_out;
    (void)in_sizes; (void)n_in; (void)out_size;

    float *xr, *sh, *eh, *eoe, *supt, *sdnt, *eupt, *ednt, *wts;
    int *counts, *rowidx, *slots;
    cudaGetSymbolAddress((void**)&xr, g_xr);
    cudaGetSymbolAddress((void**)&sh, g_sh);
    cudaGetSymbolAddress((void**)&eh, g_eh);
    cudaGetSymbolAddress((void**)&eoe, g_eoe);
    cudaGetSymbolAddress((void**)&supt, g_supt);
    cudaGetSymbolAddress((void**)&sdnt, g_sdnt);
    cudaGetSymbolAddress((void**)&eupt, g_eupt);
    cudaGetSymbolAddress((void**)&ednt, g_ednt);
    cudaGetSymbolAddress((void**)&counts, g_counts);
    cudaGetSymbolAddress((void**)&rowidx, g_rowidx);
    cudaGetSymbolAddress((void**)&slots, g_slots);
    cudaGetSymbolAddress((void**)&wts, g_wts);

    cudaFuncSetAttribute(gemm_kernel, cudaFuncAttributeMaxDynamicSharedMemorySize, 3 * STG_BYTES);
    const int gsmem = 3 * STG_BYTES;

    // 1. routing (writes xr + rowidx)
    zero_counts_kernel<<<1, 64>>>(counts);
    router_kernel<<<NTOK, 256>>>(x, rw, bias, counts, rowidx, slots, wts, xr);

    // 2. weight prep (transpose + tf32 round; up weights (y,g)-interleaved)
    transpose_round_kernel<<<dim3(2 * HS / 32, CDIM / 32, 1), dim3(32, 8)>>>(
        sup_w, supt, CDIM, 2 * HS, 0, 0, HS);
    transpose_round_kernel<<<dim3(CDIM / 32, HS / 32, 1), dim3(32, 8)>>>(
        sdown_w, sdnt, HS, CDIM, 0, 0, 0);
    transpose_round_kernel<<<dim3(2 * HE / 32, CDIM / 32, NEXP), dim3(32, 8)>>>(
        eup_w, eupt, CDIM, 2 * HE, (long)CDIM * 2 * HE, (long)2 * HE * CDIM, HE);
    transpose_round_kernel<<<dim3(CDIM / 32, HE / 32, NEXP), dim3(32, 8)>>>(
        edown_w, ednt, HE, CDIM, (long)HE * CDIM, (long)CDIM * HE, 0);

    // 3. shared expert: up(+swiglu fused) -> down
    gemm_kernel<<<dim3(2 * HS / 256, NTOK / 128, 1), 256, gsmem>>>(
        xr, supt, nullptr, sh, NTOK, 2 * HS, CDIM, 0, 0, 0, nullptr, nullptr);
    gemm_kernel<<<dim3(CDIM / 256, NTOK / 128, 1), 256, gsmem>>>(
        sh, sdnt, out, nullptr, NTOK, CDIM, HS, 0, 0, 0, nullptr, nullptr);

    // 4. expert grouped GEMMs: up(gather A + swiglu fused) -> down
    gemm_kernel<<<dim3(2 * HE / 256, CAP / 128, NEXP), 256, gsmem>>>(
        xr, eupt, nullptr, eh, CAP, 2 * HE, CDIM,
        0, (long)(2 * HE) * CDIM, (long)CAP * HE, counts, rowidx);
    gemm_kernel<<<dim3(CDIM / 256, CAP / 128, NEXP), 256, gsmem>>>(
        eh, ednt, eoe, nullptr, CAP, CDIM, HE,
        (long)CAP * HE, (long)CDIM * HE, (long)CAP * CDIM, counts, nullptr);

    // 5. combine
    combine_kernel<<<NTOK, 256>>>(eoe, slots, wts, out);
}